// round 6
// baseline (speedup 1.0000x reference)
#include <cuda_runtime.h>
#include <cuda_fp16.h>
#include <cuda_bf16.h>
#include <stdint.h>

#define SDIM 2048
#define DDIM 64
#define TQ 32
#define NTHREADS 512
#define SCH 2088            // sc row stride (u16)
#define SCW 1044            // sc row stride (u32)

// smem byte offsets
#define OFF_SC    0                  // 32*2088*2 = 133632
#define OFF_QS    133632             // 8192
#define OFF_SLOT  141824             // 4 slots * 16384 = 65536
#define OFF_SSUM  207360             // 1024
#define OFF_SINV  208384             // 128
#define OFF_MBAR  208512             // 4*8
#define SMEM_BYTES 208576

// pre-converted chunk-blocked swizzled images: [head][chunk 32][part hi/lo][2048 u32]
__device__ __align__(16) uint32_t g_k[64u * 32u * 2u * 2048u];   // bf16 hi/lo
__device__ __align__(16) uint32_t g_v[64u * 32u * 2u * 2048u];   // fp16 hi/lo, [d][key]

__device__ __forceinline__ void mma16816(float c[4], const uint32_t a[4], const uint32_t b[2]) {
    asm volatile(
        "mma.sync.aligned.m16n8k16.row.col.f32.bf16.bf16.f32 "
        "{%0,%1,%2,%3}, {%4,%5,%6,%7}, {%8,%9}, {%0,%1,%2,%3};\n"
        : "+f"(c[0]), "+f"(c[1]), "+f"(c[2]), "+f"(c[3])
        : "r"(a[0]), "r"(a[1]), "r"(a[2]), "r"(a[3]), "r"(b[0]), "r"(b[1]));
}
__device__ __forceinline__ void mma16808h(float c[4], uint32_t a0, uint32_t a1, uint32_t b0) {
    asm volatile(
        "mma.sync.aligned.m16n8k8.row.col.f32.f16.f16.f32 "
        "{%0,%1,%2,%3}, {%4,%5}, {%6}, {%0,%1,%2,%3};\n"
        : "+f"(c[0]), "+f"(c[1]), "+f"(c[2]), "+f"(c[3])
        : "r"(a0), "r"(a1), "r"(b0));
}

__device__ __forceinline__ void split2(float x, float y, uint32_t &hi, uint32_t &lo) {
    __nv_bfloat16 hx = __float2bfloat16(x);
    __nv_bfloat16 hy = __float2bfloat16(y);
    float rx = x - __bfloat162float(hx);
    float ry = y - __bfloat162float(hy);
    hi = ((uint32_t)__bfloat16_as_ushort(hy) << 16) | (uint32_t)__bfloat16_as_ushort(hx);
    lo = ((uint32_t)__bfloat16_as_ushort(__float2bfloat16(ry)) << 16) |
          (uint32_t)__bfloat16_as_ushort(__float2bfloat16(rx));
}
__device__ __forceinline__ void split1h(float x, uint16_t &h, uint16_t &l) {
    __half hx = __float2half_rn(x);
    h = __half_as_ushort(hx);
    l = __half_as_ushort(__float2half_rn(x - __half2float(hx)));
}

__device__ __forceinline__ uint32_t s2u(const void* p) {
    return (uint32_t)__cvta_generic_to_shared(p);
}
__device__ __forceinline__ void bulk_cp(uint32_t dst, const void* src, uint32_t bytes, uint32_t mbar) {
    asm volatile(
        "cp.async.bulk.shared::cluster.global.mbarrier::complete_tx::bytes [%0], [%1], %2, [%3];"
        :: "r"(dst), "l"(src), "r"(bytes), "r"(mbar) : "memory");
}
#define MBAR_INIT(mb, n) \
    asm volatile("mbarrier.init.shared.b64 [%0], %1;" :: "r"(mb), "r"(n) : "memory")
#define MBAR_EXPECT(mb, tx) \
    asm volatile("mbarrier.arrive.expect_tx.shared.b64 _, [%0], %1;" :: "r"(mb), "r"(tx) : "memory")
__device__ __forceinline__ void mbar_wait(uint32_t mb, uint32_t parity) {
    asm volatile(
        "{\n\t.reg .pred P;\n\t"
        "W_%=:\n\t"
        "mbarrier.try_wait.parity.acquire.cta.shared::cta.b64 P, [%0], %1, 0x989680;\n\t"
        "@P bra.uni D_%=;\n\t"
        "bra.uni W_%=;\n\t"
        "D_%=:\n\t}"
        :: "r"(mb), "r"(parity) : "memory");
}

// phase-stream address: [K_A nA][V_A nA][K_B nB][V_B nB], chunk index is absolute key block
__device__ __forceinline__ const uint32_t* chunk_src(
    int g, int nA, int nB, const uint32_t* kimg, const uint32_t* vimg) {
    int c; const uint32_t* base;
    if (g < nA)            { c = g;                base = kimg; }
    else if (g < 2*nA)     { c = g - nA;           base = vimg; }
    else if (g < 2*nA+nB)  { c = g - 2*nA;         base = kimg; }
    else                   { c = g - 2*nA - nB;    base = vimg; }
    return base + (size_t)c * 4096;
}

// ---------------- pre-convert ----------------
__global__ void conv_k_kernel(const float* __restrict__ kg) {
    int idx = blockIdx.x * blockDim.x + threadIdx.x;
    float4 v = ((const float4*)kg)[idx];
    int kgl = idx >> 4;
    int d4  = (idx & 15) * 4;
    int head = kgl >> 11, key = kgl & 2047;
    int chunk = key >> 6, k6 = key & 63;
    uint32_t h0, l0, h1, l1;
    split2(v.x, v.y, h0, l0);
    split2(v.z, v.w, h1, l1);
    uint32_t wp = (uint32_t)(k6 * 32 + (d4 >> 1)) ^ ((uint32_t)(k6 & 7) << 2);
    size_t base = (size_t)(head * 32 + chunk) * 2 * 2048;
    g_k[base + wp]            = h0;
    g_k[base + wp + 1]        = h1;
    g_k[base + 2048 + wp]     = l0;
    g_k[base + 2048 + wp + 1] = l1;
}

__global__ void conv_v_kernel(const float* __restrict__ vg) {
    __shared__ uint16_t th[64 * 68];
    __shared__ uint16_t tl[64 * 68];
    const int head = blockIdx.y, chunk = blockIdx.x, tid = threadIdx.x;
    const float4* src = (const float4*)(vg + ((size_t)head * SDIM + chunk * 64) * DDIM);
    #pragma unroll
    for (int rep = 0; rep < 4; ++rep) {
        int lin = tid + rep * 256;
        int key = lin >> 4, d4 = (lin & 15) * 4;
        float4 v = src[lin];
        uint16_t h, l;
        split1h(v.x, h, l); th[(d4 + 0) * 68 + key] = h; tl[(d4 + 0) * 68 + key] = l;
        split1h(v.y, h, l); th[(d4 + 1) * 68 + key] = h; tl[(d4 + 1) * 68 + key] = l;
        split1h(v.z, h, l); th[(d4 + 2) * 68 + key] = h; tl[(d4 + 2) * 68 + key] = l;
        split1h(v.w, h, l); th[(d4 + 3) * 68 + key] = h; tl[(d4 + 3) * 68 + key] = l;
    }
    __syncthreads();
    size_t base = (size_t)(head * 32 + chunk) * 2 * 2048;
    #pragma unroll
    for (int rep = 0; rep < 8; ++rep) {
        int lin = tid + rep * 256;
        int d = lin >> 5, kp = lin & 31;
        uint32_t hi = (uint32_t)th[d * 68 + kp * 2] | ((uint32_t)th[d * 68 + kp * 2 + 1] << 16);
        uint32_t lo = (uint32_t)tl[d * 68 + kp * 2] | ((uint32_t)tl[d * 68 + kp * 2 + 1] << 16);
        uint32_t wp = (uint32_t)(d * 32) + ((uint32_t)kp ^ ((uint32_t)(d & 7) << 2));
        g_v[base + wp]        = hi;
        g_v[base + 2048 + wp] = lo;
    }
}

// ---------------- fused attention: paired tiles, 2-pass per tile ----------------
__global__ __launch_bounds__(NTHREADS, 1)
void attn_kernel(const float* __restrict__ qg, float* __restrict__ outg,
                 float* __restrict__ attng)
{
    extern __shared__ char sm[];
    uint16_t* sc   = (uint16_t*)(sm + OFF_SC);
    uint32_t* scw  = (uint32_t*)(sm + OFF_SC);
    float*    qs   = (float*)(sm + OFF_QS);
    uint32_t* slots= (uint32_t*)(sm + OFF_SLOT);
    float*    ssum = (float*)(sm + OFF_SSUM);
    float*    sinv = (float*)(sm + OFF_SINV);

    const int bh = blockIdx.y;
    const int pr = blockIdx.x;                   // pair id
    const int tid = threadIdx.x, lane = tid & 31, wid = tid >> 5;
    const int w7 = wid & 7, rbase = (wid >= 8) ? 16 : 0;
    const int r4 = lane >> 2, l3 = lane & 3, c0 = l3 * 2;
    const uint32_t xm = (uint32_t)(lane >> 2) << 2;

    const size_t headoff = (size_t)bh * SDIM * DDIM;
    const uint32_t* kimg = g_k + (size_t)bh * 32 * 4096;
    const uint32_t* vimg = g_v + (size_t)bh * 32 * 4096;

    const int qbA = pr * TQ, qbB = (63 - pr) * TQ;
    const int nA = (qbA + TQ + 63) >> 6, nB = (qbB + TQ + 63) >> 6;
    const int T = 2 * (nA + nB);

    const uint32_t mbb = s2u(sm + OFF_MBAR);
    if (tid == 0) {
        #pragma unroll
        for (int s = 0; s < 4; ++s) MBAR_INIT(mbb + 8 * s, 1);
    }
    __syncthreads();
    if (tid == 0) {
        #pragma unroll
        for (int gg = 0; gg < 3; ++gg) {    // T >= 66 always
            MBAR_EXPECT(mbb + 8 * gg, 16384);
            bulk_cp(s2u(slots + gg * 4096), chunk_src(gg, nA, nB, kimg, vimg),
                    16384, mbb + 8 * gg);
        }
    }

    int g = 0;
    #pragma unroll 1
    for (int t = 0; t < 2; ++t) {
        const int qbase = t ? qbB : qbA;
        const int n     = t ? nB  : nA;
        const int cendC = n * 64;

        __syncthreads();                       // everyone done with prev tile
        for (int i = tid; i < TQ * DDIM; i += NTHREADS)
            qs[i] = qg[headoff + (size_t)qbase * DDIM + i] * 0.125f;
        __syncthreads();

        // Q A-fragments (bf16 hi/lo)
        uint32_t aqh[4][4], aql[4][4];
        #pragma unroll
        for (int ks = 0; ks < 4; ++ks) {
            const float* q0 = qs + (rbase + r4) * DDIM + ks * 16;
            const float* q1 = q0 + 8 * DDIM;
            split2(q0[c0],     q0[c0 + 1], aqh[ks][0], aql[ks][0]);
            split2(q1[c0],     q1[c0 + 1], aqh[ks][1], aql[ks][1]);
            split2(q0[c0 + 8], q0[c0 + 9], aqh[ks][2], aql[ks][2]);
            split2(q1[c0 + 8], q1[c0 + 9], aqh[ks][3], aql[ks][3]);
        }

        // ---------------- pass 1: QK + exp + sums + sc ----------------
        float s0 = 0.f, s1 = 0.f;
        const int row0 = qbase + rbase + r4, row1 = row0 + 8;
        const int kwb  = (w7 * 8 + (lane >> 2)) * 32;

        #pragma unroll 1
        for (int c = 0; c < n; ++c, ++g) {
            __syncthreads();
            if (tid == 0 && g + 3 < T) {
                int s = (g + 3) & 3;
                MBAR_EXPECT(mbb + 8 * s, 16384);
                bulk_cp(s2u(slots + s * 4096), chunk_src(g + 3, nA, nB, kimg, vimg),
                        16384, mbb + 8 * s);
            }
            mbar_wait(mbb + 8 * (g & 3), (uint32_t)((g >> 2) & 1));

            const uint32_t* kh = slots + (g & 3) * 4096;
            const uint32_t* kl = kh + 2048;
            float a0[4] = {0,0,0,0}, a1[4] = {0,0,0,0};
            float a2[4] = {0,0,0,0}, a3[4] = {0,0,0,0};
            #define QKS(ACC, KS) { \
                uint32_t i0 = kwb + (((uint32_t)((KS)*8 + l3))     ^ xm); \
                uint32_t i1 = kwb + (((uint32_t)((KS)*8 + l3 + 4)) ^ xm); \
                uint32_t bh2[2] = {kh[i0], kh[i1]}; \
                uint32_t bl2[2] = {kl[i0], kl[i1]}; \
                mma16816(ACC, aqh[KS], bh2); \
                mma16816(ACC, aql[KS], bh2); \
                mma16816(ACC, aqh[KS], bl2); }
            QKS(a0, 0) QKS(a1, 1) QKS(a2, 2) QKS(a3, 3)
            #undef QKS

            const float acc0 = (a0[0] + a1[0]) + (a2[0] + a3[0]);
            const float acc1 = (a0[1] + a1[1]) + (a2[1] + a3[1]);
            const float acc2 = (a0[2] + a1[2]) + (a2[2] + a3[2]);
            const float acc3 = (a0[3] + a1[3]) + (a2[3] + a3[3]);

            const int col = c * 64 + w7 * 8 + c0;
            float p0 = (col     <= row0) ? __expf(acc0) : 0.f;
            float p1 = (col + 1 <= row0) ? __expf(acc1) : 0.f;
            float p2 = (col     <= row1) ? __expf(acc2) : 0.f;
            float p3 = (col + 1 <= row1) ? __expf(acc3) : 0.f;
            s0 += p0 + p1;
            s1 += p2 + p3;

            __half2 h01 = __floats2half2_rn(p0, p1);
            __half2 h23 = __floats2half2_rn(p2, p3);
            scw[(rbase + r4) * SCW     + (col >> 1)] = *(uint32_t*)&h01;
            scw[(rbase + r4 + 8) * SCW + (col >> 1)] = *(uint32_t*)&h23;
        }

        // ---------------- row sums -> sinv ----------------
        s0 += __shfl_xor_sync(0xffffffffu, s0, 1);
        s0 += __shfl_xor_sync(0xffffffffu, s0, 2);
        s1 += __shfl_xor_sync(0xffffffffu, s1, 1);
        s1 += __shfl_xor_sync(0xffffffffu, s1, 2);
        if (l3 == 0) {
            ssum[(rbase + r4) * 8 + w7]     = s0;
            ssum[(rbase + r4 + 8) * 8 + w7] = s1;
        }
        __syncthreads();
        if (tid < TQ) {
            float s = 0.f;
            #pragma unroll
            for (int w = 0; w < 8; ++w) s += ssum[tid * 8 + w];
            sinv[tid] = 1.0f / s;
        }
        __syncthreads();

        // ---------------- pass 2: PV (fp16) + interleaved attn write ----------------
        float oc[4] = {0.f, 0.f, 0.f, 0.f};
        const int dloc = w7 * 8 + (lane >> 2);
        const float invr = sinv[tid >> 4];
        float* arow = attng ? attng + ((size_t)bh * SDIM + qbase + (tid >> 4)) * SDIM
                            : (float*)0;

        #pragma unroll 1
        for (int c = 0; c < n; ++c, ++g) {
            __syncthreads();
            if (tid == 0 && g + 3 < T) {
                int s = (g + 3) & 3;
                MBAR_EXPECT(mbb + 8 * s, 16384);
                bulk_cp(s2u(slots + s * 4096), chunk_src(g + 3, nA, nB, kimg, vimg),
                        16384, mbb + 8 * s);
            }
            mbar_wait(mbb + 8 * (g & 3), (uint32_t)((g >> 2) & 1));

            const uint32_t* vh = slots + (g & 3) * 4096;
            const int cb2 = c * 32;
            #pragma unroll
            for (int kg = 0; kg < 8; ++kg) {
                uint32_t pa0 = scw[(rbase + r4) * SCW     + cb2 + kg * 4 + l3];
                uint32_t pa1 = scw[(rbase + r4 + 8) * SCW + cb2 + kg * 4 + l3];
                uint32_t vi = (uint32_t)(dloc * 32) + (((uint32_t)(kg * 4 + l3)) ^ xm);
                mma16808h(oc, pa0, pa1, vh[vi]);
                mma16808h(oc, pa0, pa1, vh[2048 + vi]);
            }

            if (arow) {
                const int jc = c * 64 + (tid & 15) * 4;
                uint2 pk = *(const uint2*)(sc + (tid >> 4) * SCH + jc);
                float2 fa = __half22float2(*(__half2*)&pk.x);
                float2 fb = __half22float2(*(__half2*)&pk.y);
                __stcs((float4*)(arow + jc),
                       make_float4(fa.x * invr, fa.y * invr, fb.x * invr, fb.y * invr));
            }
        }

        // attn tail zeros (cols >= cendC)
        if (arow) {
            for (int j = cendC + (tid & 15) * 4; j < SDIM; j += 64)
                __stcs((float4*)(arow + j), make_float4(0.f, 0.f, 0.f, 0.f));
        }

        // output write (warp-owned 16x8 block, no reduction needed)
        {
            const float sv0 = sinv[rbase + r4], sv1 = sinv[rbase + r4 + 8];
            float* orow = outg + headoff + (size_t)(qbase + rbase + r4) * DDIM;
            const int dc = w7 * 8 + c0;
            *(float2*)(orow + dc)            = make_float2(oc[0] * sv0, oc[1] * sv0);
            *(float2*)(orow + 8 * DDIM + dc) = make_float2(oc[2] * sv1, oc[3] * sv1);
        }
    }
}

extern "C" void kernel_launch(void* const* d_in, const int* in_sizes, int n_in,
                              void* d_out, int out_size) {
    const float* q = (const float*)d_in[0];
    const float* k = (const float*)d_in[1];
    const float* v = (const float*)d_in[2];

    float* out = (float*)d_out;
    const long long OUT_E  = 64LL * 2048 * 64;
    const long long ATTN_E = 64LL * 2048 * 2048;
    float* attn = ((long long)out_size >= OUT_E + ATTN_E) ? out + OUT_E : nullptr;

    conv_k_kernel<<<8192, 256>>>(k);
    {
        dim3 g(32, 64);
        conv_v_kernel<<<g, 256>>>(v);
    }

    cudaFuncSetAttribute(attn_kernel,
                         cudaFuncAttributeMaxDynamicSharedMemorySize, SMEM_BYTES);
    dim3 grid(32, 64);   // 32 balanced tile-pairs x 64 heads
    attn_kernel<<<grid, NTHREADS, SMEM_BYTES>>>(q, out, attn);
}